// round 3
// baseline (speedup 1.0000x reference)
#include <cuda_runtime.h>

// GIN embedder: 5x [aggregate -> Linear -> BN -> ReLU -> Linear -> ReLU],
// jumping-knowledge concat, final Linear-BN-ReLU-Linear, global add pool.
// N=50000 nodes, E=800000 edges, H=64.

#define HDIM 64
#define NMAX 50000
#define EMAX 800000
#define NV4  (NMAX * 16)   // float4 count per feature buffer

// Scratch as float4 so every vector access / v4 red is 16B-aligned.
__device__ float4 g_h4[5][NV4];   // per-layer node features h1..h5
__device__ float4 g_aggr4[NV4];   // neighbor-sum buffer
__device__ float4 g_t4[NV4];      // pre-BN intermediate
__device__ float  g_stats[128];   // [sum(64), sumsq(64)]
__device__ int    g_src[EMAX];    // normalized int32 indices
__device__ int    g_dst[EMAX];
__device__ int    g_batch[NMAX];
__device__ int    g_is64;         // 1 if harness indices are int64

// ---------------------------------------------------------------------------
// helpers
// ---------------------------------------------------------------------------
__device__ __forceinline__ void fma64(float* acc, float z, const float* Wrow) {
    const float4* w4 = (const float4*)Wrow;   // broadcast LDS.128, conflict-free
#pragma unroll
    for (int c = 0; c < 16; c++) {
        float4 w = w4[c];
        acc[4 * c + 0] = fmaf(z, w.x, acc[4 * c + 0]);
        acc[4 * c + 1] = fmaf(z, w.y, acc[4 * c + 1]);
        acc[4 * c + 2] = fmaf(z, w.z, acc[4 * c + 2]);
        acc[4 * c + 3] = fmaf(z, w.w, acc[4 * c + 3]);
    }
}

__device__ __forceinline__ void red_add_v4(float* p, float a, float b, float c, float d) {
    asm volatile("red.global.add.v4.f32 [%0], {%1,%2,%3,%4};"
                 :: "l"(p), "f"(a), "f"(b), "f"(c), "f"(d) : "memory");
}

// ---------------------------------------------------------------------------
// index dtype probe: int64 LE data has zero in every odd 32-bit word.
// ---------------------------------------------------------------------------
__global__ void k_probe(const unsigned int* __restrict__ ei_raw, int nwords) {
    __shared__ int any_nonzero;
    if (threadIdx.x == 0) any_nonzero = 0;
    __syncthreads();
    for (int i = threadIdx.x; i < nwords / 2; i += blockDim.x)
        if (ei_raw[2 * i + 1] != 0u) any_nonzero = 1;
    __syncthreads();
    if (threadIdx.x == 0) g_is64 = any_nonzero ? 0 : 1;
}

// normalize edge_index + batch into int32 scratch
__global__ void k_convert(const void* __restrict__ ei, const void* __restrict__ batch,
                          int E, int N) {
    int i = blockIdx.x * blockDim.x + threadIdx.x;
    bool is64 = (g_is64 != 0);
    if (i < E) {
        if (is64) {
            g_src[i] = (int)((const long long*)ei)[i];
            g_dst[i] = (int)((const long long*)ei)[E + i];
        } else {
            g_src[i] = ((const int*)ei)[i];
            g_dst[i] = ((const int*)ei)[E + i];
        }
    }
    if (i < N) {
        g_batch[i] = is64 ? (int)((const long long*)batch)[i]
                          : ((const int*)batch)[i];
    }
}

// zero aggr[0..n4) and stats[0..128)
__global__ void k_zero(int n4) {
    int i = blockIdx.x * blockDim.x + threadIdx.x;
    if (i < n4) g_aggr4[i] = make_float4(0.f, 0.f, 0.f, 0.f);
    if (i < 128) g_stats[i] = 0.f;
}

__global__ void k_zero_stats() {
    if (threadIdx.x < 128) g_stats[threadIdx.x] = 0.f;
}

// ---------------------------------------------------------------------------
// edge aggregation: aggr[dst] += h[src]   (16 threads per edge, float4 each)
// hidx < 0 -> source features are x; else g_h4[hidx]
// ---------------------------------------------------------------------------
__global__ void k_aggregate(int hidx, const float4* __restrict__ x4, int E) {
    const float4* h4 = (hidx < 0) ? x4 : (const float4*)g_h4[hidx];
    int tid = blockIdx.x * blockDim.x + threadIdx.x;
    int e = tid >> 4;
    if (e >= E) return;
    int j = tid & 15;
    int s = __ldg(&g_src[e]);
    int d = __ldg(&g_dst[e]);
    float4 v = __ldg(&h4[s * 16 + j]);
    red_add_v4((float*)(&g_aggr4[d * 16 + j]), v.x, v.y, v.z, v.w);
}

// ---------------------------------------------------------------------------
// GEMM1: t = (h + aggr) @ W1 + b1        (one row per thread)
// ---------------------------------------------------------------------------
__global__ void __launch_bounds__(256, 2)
k_gemm1(int hidx, const float4* __restrict__ x4,
        const float* __restrict__ W, const float* __restrict__ b, int N) {
    const float4* h4 = (hidx < 0) ? x4 : (const float4*)g_h4[hidx];
    __shared__ __align__(16) float Ws[64 * 64];
    __shared__ float bs[64];
    int tid = threadIdx.x;
    for (int i = tid; i < 1024; i += 256)
        ((float4*)Ws)[i] = ((const float4*)W)[i];
    if (tid < 64) bs[tid] = b[tid];
    __syncthreads();

    int r = blockIdx.x * 256 + tid;
    if (r >= N) return;

    float acc[64];
#pragma unroll
    for (int c = 0; c < 64; c++) acc[c] = bs[c];

#pragma unroll
    for (int k4 = 0; k4 < 16; k4++) {
        float4 zh = h4[r * 16 + k4];
        float4 za = g_aggr4[r * 16 + k4];
        fma64(acc, zh.x + za.x, Ws + (k4 * 4 + 0) * 64);
        fma64(acc, zh.y + za.y, Ws + (k4 * 4 + 1) * 64);
        fma64(acc, zh.z + za.z, Ws + (k4 * 4 + 2) * 64);
        fma64(acc, zh.w + za.w, Ws + (k4 * 4 + 3) * 64);
    }
#pragma unroll
    for (int c4 = 0; c4 < 16; c4++)
        g_t4[r * 16 + c4] = make_float4(acc[4 * c4], acc[4 * c4 + 1],
                                        acc[4 * c4 + 2], acc[4 * c4 + 3]);
}

// ---------------------------------------------------------------------------
// column sums + sumsq of t  (for BatchNorm batch stats)
// ---------------------------------------------------------------------------
__global__ void k_stats(int n4) {
    __shared__ float sh[8][128];
    int tid = threadIdx.x;
    float s0 = 0, s1 = 0, s2 = 0, s3 = 0, q0 = 0, q1 = 0, q2 = 0, q3 = 0;
    // stride and base are multiples of 16 -> column group fixed per thread
    for (int i = blockIdx.x * blockDim.x + tid; i < n4; i += gridDim.x * blockDim.x) {
        float4 v = g_t4[i];
        s0 += v.x; q0 += v.x * v.x;
        s1 += v.y; q1 += v.y * v.y;
        s2 += v.z; q2 += v.z * v.z;
        s3 += v.w; q3 += v.w * v.w;
    }
    // lanes j and j+16 hold the same column group
    s0 += __shfl_down_sync(~0u, s0, 16); s1 += __shfl_down_sync(~0u, s1, 16);
    s2 += __shfl_down_sync(~0u, s2, 16); s3 += __shfl_down_sync(~0u, s3, 16);
    q0 += __shfl_down_sync(~0u, q0, 16); q1 += __shfl_down_sync(~0u, q1, 16);
    q2 += __shfl_down_sync(~0u, q2, 16); q3 += __shfl_down_sync(~0u, q3, 16);
    int lane = tid & 31, warp = tid >> 5;
    if (lane < 16) {
        int base = lane * 8;
        sh[warp][base + 0] = s0; sh[warp][base + 1] = s1;
        sh[warp][base + 2] = s2; sh[warp][base + 3] = s3;
        sh[warp][base + 4] = q0; sh[warp][base + 5] = q1;
        sh[warp][base + 6] = q2; sh[warp][base + 7] = q3;
    }
    __syncthreads();
    if (tid < 128) {
        float tot = 0;
#pragma unroll
        for (int w = 0; w < 8; w++) tot += sh[w][tid];
        int g = tid >> 3, v = tid & 7;
        int c = g * 4 + (v & 3);
        atomicAdd(&g_stats[(v < 4 ? 0 : 64) + c], tot);
    }
}

// ---------------------------------------------------------------------------
// GEMM2: h[outIdx] = relu( relu(BN(t)) @ W2 + b2 )
// ---------------------------------------------------------------------------
__global__ void __launch_bounds__(256, 2)
k_gemm2(int outIdx, const float* __restrict__ W, const float* __restrict__ b,
        const float* __restrict__ gam, const float* __restrict__ bet,
        int N, float invN) {
    __shared__ __align__(16) float Ws[64 * 64];
    __shared__ __align__(16) float bs[64], sc[64], sf[64];
    int tid = threadIdx.x;
    for (int i = tid; i < 1024; i += 256)
        ((float4*)Ws)[i] = ((const float4*)W)[i];
    if (tid < 64) {
        bs[tid] = b[tid];
        float mu = g_stats[tid] * invN;
        float var = g_stats[64 + tid] * invN - mu * mu;
        float s = gam[tid] * rsqrtf(var + 1e-5f);
        sc[tid] = s;
        sf[tid] = bet[tid] - mu * s;
    }
    __syncthreads();

    int r = blockIdx.x * 256 + tid;
    if (r >= N) return;

    float acc[64];
#pragma unroll
    for (int c = 0; c < 64; c++) acc[c] = bs[c];

#pragma unroll
    for (int k4 = 0; k4 < 16; k4++) {
        float4 tv = g_t4[r * 16 + k4];
        float4 c4 = ((const float4*)sc)[k4];
        float4 f4 = ((const float4*)sf)[k4];
        fma64(acc, fmaxf(fmaf(tv.x, c4.x, f4.x), 0.f), Ws + (k4 * 4 + 0) * 64);
        fma64(acc, fmaxf(fmaf(tv.y, c4.y, f4.y), 0.f), Ws + (k4 * 4 + 1) * 64);
        fma64(acc, fmaxf(fmaf(tv.z, c4.z, f4.z), 0.f), Ws + (k4 * 4 + 2) * 64);
        fma64(acc, fmaxf(fmaf(tv.w, c4.w, f4.w), 0.f), Ws + (k4 * 4 + 3) * 64);
    }
#pragma unroll
    for (int c4 = 0; c4 < 16; c4++)
        g_h4[outIdx][r * 16 + c4] = make_float4(fmaxf(acc[4 * c4 + 0], 0.f),
                                                fmaxf(acc[4 * c4 + 1], 0.f),
                                                fmaxf(acc[4 * c4 + 2], 0.f),
                                                fmaxf(acc[4 * c4 + 3], 0.f));
}

// ---------------------------------------------------------------------------
// Final MLP GEMM1: t = concat(x, h1..h5) @ mlpW1[384][64] + b1  (chunked K)
// ---------------------------------------------------------------------------
__global__ void __launch_bounds__(256, 2)
k_gemmF1(const float4* __restrict__ x4, const float* __restrict__ W,
         const float* __restrict__ b, int N) {
    __shared__ __align__(16) float Ws[64 * 64];
    __shared__ float bs[64];
    int tid = threadIdx.x;
    if (tid < 64) bs[tid] = b[tid];
    __syncthreads();

    int r = blockIdx.x * 256 + tid;
    bool act = (r < N);
    float acc[64];
    if (act) {
#pragma unroll
        for (int c = 0; c < 64; c++) acc[c] = bs[c];
    }

    for (int blk = 0; blk < 6; blk++) {
        __syncthreads();
        for (int i = tid; i < 1024; i += 256)
            ((float4*)Ws)[i] = ((const float4*)(W + blk * 4096))[i];
        __syncthreads();
        const float4* src4 = (blk == 0) ? x4 : (const float4*)g_h4[blk - 1];
        if (act) {
#pragma unroll
            for (int k4 = 0; k4 < 16; k4++) {
                float4 z = src4[r * 16 + k4];
                fma64(acc, z.x, Ws + (k4 * 4 + 0) * 64);
                fma64(acc, z.y, Ws + (k4 * 4 + 1) * 64);
                fma64(acc, z.z, Ws + (k4 * 4 + 2) * 64);
                fma64(acc, z.w, Ws + (k4 * 4 + 3) * 64);
            }
        }
    }
    if (act) {
#pragma unroll
        for (int c4 = 0; c4 < 16; c4++)
            g_t4[r * 16 + c4] = make_float4(acc[4 * c4], acc[4 * c4 + 1],
                                            acc[4 * c4 + 2], acc[4 * c4 + 3]);
    }
}

// ---------------------------------------------------------------------------
// Final MLP GEMM2 + global add pool:
//   y = relu(BN(t)) @ mlpW2 + b2;  out[batch[r]] += y
// ---------------------------------------------------------------------------
__global__ void __launch_bounds__(256, 2)
k_gemmF2(const float* __restrict__ W, const float* __restrict__ b,
         const float* __restrict__ gam, const float* __restrict__ bet,
         float* __restrict__ out, int N, float invN) {
    __shared__ __align__(16) float Ws[64 * 64];
    __shared__ __align__(16) float bs[64], sc[64], sf[64];
    int tid = threadIdx.x;
    for (int i = tid; i < 1024; i += 256)
        ((float4*)Ws)[i] = ((const float4*)W)[i];
    if (tid < 64) {
        bs[tid] = b[tid];
        float mu = g_stats[tid] * invN;
        float var = g_stats[64 + tid] * invN - mu * mu;
        float s = gam[tid] * rsqrtf(var + 1e-5f);
        sc[tid] = s;
        sf[tid] = bet[tid] - mu * s;
    }
    __syncthreads();

    int r = blockIdx.x * 256 + tid;
    if (r >= N) return;

    float acc[64];
#pragma unroll
    for (int c = 0; c < 64; c++) acc[c] = bs[c];

#pragma unroll
    for (int k4 = 0; k4 < 16; k4++) {
        float4 tv = g_t4[r * 16 + k4];
        float4 c4 = ((const float4*)sc)[k4];
        float4 f4 = ((const float4*)sf)[k4];
        fma64(acc, fmaxf(fmaf(tv.x, c4.x, f4.x), 0.f), Ws + (k4 * 4 + 0) * 64);
        fma64(acc, fmaxf(fmaf(tv.y, c4.y, f4.y), 0.f), Ws + (k4 * 4 + 1) * 64);
        fma64(acc, fmaxf(fmaf(tv.z, c4.z, f4.z), 0.f), Ws + (k4 * 4 + 2) * 64);
        fma64(acc, fmaxf(fmaf(tv.w, c4.w, f4.w), 0.f), Ws + (k4 * 4 + 3) * 64);
    }

    int grp = __ldg(&g_batch[r]);
    float* o = out + grp * 64;
#pragma unroll
    for (int c4 = 0; c4 < 16; c4++)
        red_add_v4(o + c4 * 4, acc[4 * c4], acc[4 * c4 + 1],
                   acc[4 * c4 + 2], acc[4 * c4 + 3]);
}

// ---------------------------------------------------------------------------
// launch
// ---------------------------------------------------------------------------
extern "C" void kernel_launch(void* const* d_in, const int* in_sizes, int n_in,
                              void* d_out, int out_size) {
    const float* x      = (const float*)d_in[0];
    const void*  ei     = d_in[1];
    const void*  batch  = d_in[2];
    const float* convW1 = (const float*)d_in[3];
    const float* convb1 = (const float*)d_in[4];
    const float* convg  = (const float*)d_in[5];
    const float* convbt = (const float*)d_in[6];
    const float* convW2 = (const float*)d_in[7];
    const float* convb2 = (const float*)d_in[8];
    const float* mlpW1  = (const float*)d_in[9];
    const float* mlpb1  = (const float*)d_in[10];
    const float* mlpg   = (const float*)d_in[11];
    const float* mlpbt  = (const float*)d_in[12];
    const float* mlpW2  = (const float*)d_in[13];
    const float* mlpb2  = (const float*)d_in[14];

    int N = in_sizes[0] / HDIM;
    int E = in_sizes[1] / 2;

    const int NB = (N + 255) / 256;
    const int AB = (E * 16 + 255) / 256;
    const int ZB = (N * 16 + 255) / 256;
    const int CB = ((E > N ? E : N) + 255) / 256;
    const float invN = 1.0f / (float)N;

    cudaMemsetAsync(d_out, 0, (size_t)out_size * sizeof(float));

    // normalize index dtype (int32 vs int64) into int32 scratch
    int probe_words = 4096;
    if (probe_words > 2 * E) probe_words = 2 * E;
    k_probe<<<1, 256>>>((const unsigned int*)ei, probe_words);
    k_convert<<<CB, 256>>>(ei, batch, E, N);

    for (int l = 0; l < 5; l++) {
        int hidx = l - 1;                       // -1 -> x, else g_h4[l-1]
        k_zero<<<ZB, 256>>>(N * 16);
        k_aggregate<<<AB, 256>>>(hidx, (const float4*)x, E);
        k_gemm1<<<NB, 256>>>(hidx, (const float4*)x,
                             convW1 + l * 4096, convb1 + l * 64, N);
        k_stats<<<256, 256>>>(N * 16);
        k_gemm2<<<NB, 256>>>(l, convW2 + l * 4096, convb2 + l * 64,
                             convg + l * 64, convbt + l * 64, N, invN);
    }

    // final MLP + pool
    k_gemmF1<<<NB, 256>>>((const float4*)x, mlpW1, mlpb1, N);
    k_zero_stats<<<1, 128>>>();
    k_stats<<<256, 256>>>(N * 16);
    k_gemmF2<<<NB, 256>>>(mlpW2, mlpb2, mlpg, mlpbt, (float*)d_out, N, invN);
}

// round 4
// speedup vs baseline: 1.1833x; 1.1833x over previous
#include <cuda_runtime.h>

// GIN embedder: 5x [aggregate -> Linear -> BN -> ReLU -> Linear -> ReLU],
// jumping-knowledge concat, final Linear-BN-ReLU-Linear, global add pool.
// N=50000 nodes, E=800000 edges, H=64.
// R4: CSR gather aggregation (no atomics) + fma.rn.f32x2 GEMMs.

#define HDIM 64
#define NMAX 50000
#define EMAX 800000
#define NV4  (NMAX * 16)   // float4 count per feature buffer

__device__ float4 g_h4[5][NV4];   // per-layer node features h1..h5
__device__ float4 g_aggr4[NV4];   // h + neighbor-sum buffer
__device__ float4 g_t4[NV4];      // pre-BN intermediate
__device__ float  g_stats[128];   // [sum(64), sumsq(64)]
__device__ int    g_src[EMAX];    // normalized int32 indices
__device__ int    g_dst[EMAX];
__device__ int    g_batch[NMAX];
__device__ int    g_is64;         // 1 if harness indices are int64
// CSR scratch
__device__ int    g_cnt[NMAX];
__device__ int    g_rowptr[NMAX + 1];
__device__ int    g_cursor[NMAX];
__device__ int    g_csr[EMAX];
__device__ int    g_bsum[256];

// ---------------------------------------------------------------------------
// helpers
// ---------------------------------------------------------------------------
__device__ __forceinline__ unsigned long long pack2(float a, float b) {
    unsigned long long r;
    asm("mov.b64 %0, {%1, %2};" : "=l"(r) : "f"(a), "f"(b));
    return r;
}
__device__ __forceinline__ float2 unpk(unsigned long long v) {
    float2 r;
    asm("mov.b64 {%0, %1}, %2;" : "=f"(r.x), "=f"(r.y) : "l"(v));
    return r;
}

// acc2[32] over 64 columns; one rank-1 update with scalar z (FFMA2 pipe).
__device__ __forceinline__ void fma64_2(unsigned long long* acc2, float z,
                                        const float* Wrow) {
    unsigned long long zz;
    asm("mov.b64 %0, {%1, %1};" : "=l"(zz) : "f"(z));
    const float4* w4 = (const float4*)Wrow;
#pragma unroll
    for (int c = 0; c < 16; c++) {
        float4 w = w4[c];
        unsigned long long w01 = pack2(w.x, w.y);
        unsigned long long w23 = pack2(w.z, w.w);
        asm("fma.rn.f32x2 %0, %1, %2, %0;" : "+l"(acc2[2 * c])     : "l"(zz), "l"(w01));
        asm("fma.rn.f32x2 %0, %1, %2, %0;" : "+l"(acc2[2 * c + 1]) : "l"(zz), "l"(w23));
    }
}

__device__ __forceinline__ void red_add_v4(float* p, float a, float b, float c, float d) {
    asm volatile("red.global.add.v4.f32 [%0], {%1,%2,%3,%4};"
                 :: "l"(p), "f"(a), "f"(b), "f"(c), "f"(d) : "memory");
}

// ---------------------------------------------------------------------------
// index dtype probe + conversion
// ---------------------------------------------------------------------------
__global__ void k_probe(const unsigned int* __restrict__ ei_raw, int nwords) {
    __shared__ int any_nonzero;
    if (threadIdx.x == 0) any_nonzero = 0;
    __syncthreads();
    for (int i = threadIdx.x; i < nwords / 2; i += blockDim.x)
        if (ei_raw[2 * i + 1] != 0u) any_nonzero = 1;
    __syncthreads();
    if (threadIdx.x == 0) g_is64 = any_nonzero ? 0 : 1;
}

__global__ void k_convert(const void* __restrict__ ei, const void* __restrict__ batch,
                          int E, int N) {
    int i = blockIdx.x * blockDim.x + threadIdx.x;
    bool is64 = (g_is64 != 0);
    if (i < E) {
        if (is64) {
            g_src[i] = (int)((const long long*)ei)[i];
            g_dst[i] = (int)((const long long*)ei)[E + i];
        } else {
            g_src[i] = ((const int*)ei)[i];
            g_dst[i] = ((const int*)ei)[E + i];
        }
    }
    if (i < N) {
        g_batch[i] = is64 ? (int)((const long long*)batch)[i]
                          : ((const int*)batch)[i];
    }
}

// ---------------------------------------------------------------------------
// CSR build: zero counts -> histogram -> 2-level exclusive scan -> scatter
// ---------------------------------------------------------------------------
__global__ void k_zero_cnt(int N) {
    int i = blockIdx.x * blockDim.x + threadIdx.x;
    if (i < N) g_cnt[i] = 0;
}

__global__ void k_hist(int E) {
    int e = blockIdx.x * blockDim.x + threadIdx.x;
    if (e < E) atomicAdd(&g_cnt[g_dst[e]], 1);
}

// block sums of 256-chunks
__global__ void k_scan1(int N) {
    __shared__ int sh[256];
    int i = blockIdx.x * 256 + threadIdx.x;
    int v = (i < N) ? g_cnt[i] : 0;
    sh[threadIdx.x] = v;
    __syncthreads();
    // tree reduce
    for (int s = 128; s > 0; s >>= 1) {
        if (threadIdx.x < s) sh[threadIdx.x] += sh[threadIdx.x + s];
        __syncthreads();
    }
    if (threadIdx.x == 0) g_bsum[blockIdx.x] = sh[0];
}

// exclusive scan of block sums (nblk <= 256), single block
__global__ void k_scan2(int nblk) {
    __shared__ int a[256], b[256];
    int t = threadIdx.x;
    a[t] = (t < nblk) ? g_bsum[t] : 0;
    __syncthreads();
    int* cur = a; int* nxt = b;
    for (int off = 1; off < 256; off <<= 1) {
        nxt[t] = cur[t] + ((t >= off) ? cur[t - off] : 0);
        __syncthreads();
        int* tmp = cur; cur = nxt; nxt = tmp;
    }
    if (t < nblk) g_bsum[t] = cur[t] - ((t < nblk) ? ((t == 0) ? cur[0] : cur[t] - cur[t - 1]) : 0) * 0
                              - 0;   // inclusive; convert below
    // write exclusive: sum of all before t
    __syncthreads();
    if (t < nblk) g_bsum[t] = (t == 0) ? 0 : cur[t - 1];
}

// per-block exclusive scan + offset -> rowptr, cursor
__global__ void k_scan3(int N) {
    __shared__ int a[256], b[256];
    int t = threadIdx.x;
    int i = blockIdx.x * 256 + t;
    int v = (i < N) ? g_cnt[i] : 0;
    a[t] = v;
    __syncthreads();
    int* cur = a; int* nxt = b;
    for (int off = 1; off < 256; off <<= 1) {
        nxt[t] = cur[t] + ((t >= off) ? cur[t - off] : 0);
        __syncthreads();
        int* tmp = cur; cur = nxt; nxt = tmp;
    }
    int excl = cur[t] - v;
    int row = g_bsum[blockIdx.x] + excl;
    if (i <= N) {
        g_rowptr[i] = row;
        if (i < N) g_cursor[i] = row;
    }
}

__global__ void k_scatter(int E) {
    int e = blockIdx.x * blockDim.x + threadIdx.x;
    if (e >= E) return;
    int d = g_dst[e];
    int pos = atomicAdd(&g_cursor[d], 1);
    g_csr[pos] = g_src[e];
}

// ---------------------------------------------------------------------------
// gather aggregation: aggr[n] = h[n] + sum_{j in nbrs(n)} h[j]
// 16 threads per node (one float4 lane each)
// ---------------------------------------------------------------------------
__global__ void k_gather(int hidx, const float4* __restrict__ x4, int N) {
    const float4* h4 = (hidx < 0) ? x4 : (const float4*)g_h4[hidx];
    int tid = blockIdx.x * blockDim.x + threadIdx.x;
    int n = tid >> 4;
    if (n >= N) return;
    int j = tid & 15;
    int beg = __ldg(&g_rowptr[n]);
    int end = __ldg(&g_rowptr[n + 1]);
    float4 acc = __ldg(&h4[n * 16 + j]);   // self term (GIN eps=0)
    for (int i = beg; i < end; i++) {
        int s = __ldg(&g_csr[i]);
        float4 v = __ldg(&h4[s * 16 + j]);
        acc.x += v.x; acc.y += v.y; acc.z += v.z; acc.w += v.w;
    }
    g_aggr4[n * 16 + j] = acc;
}

// ---------------------------------------------------------------------------
// GEMM1: t = aggr @ W1 + b1        (one row per thread, FFMA2)
// ---------------------------------------------------------------------------
__global__ void __launch_bounds__(256, 2)
k_gemm1(const float* __restrict__ W, const float* __restrict__ b, int N) {
    __shared__ __align__(16) float Ws[64 * 64];
    __shared__ __align__(16) float bs[64];
    int tid = threadIdx.x;
    for (int i = tid; i < 1024; i += 256)
        ((float4*)Ws)[i] = ((const float4*)W)[i];
    if (tid < 64) bs[tid] = b[tid];
    __syncthreads();

    int r = blockIdx.x * 256 + tid;
    if (r >= N) return;

    unsigned long long acc2[32];
#pragma unroll
    for (int c = 0; c < 16; c++) {
        float4 bv = ((const float4*)bs)[c];
        acc2[2 * c]     = pack2(bv.x, bv.y);
        acc2[2 * c + 1] = pack2(bv.z, bv.w);
    }

#pragma unroll
    for (int k4 = 0; k4 < 16; k4++) {
        float4 z = g_aggr4[r * 16 + k4];
        fma64_2(acc2, z.x, Ws + (k4 * 4 + 0) * 64);
        fma64_2(acc2, z.y, Ws + (k4 * 4 + 1) * 64);
        fma64_2(acc2, z.z, Ws + (k4 * 4 + 2) * 64);
        fma64_2(acc2, z.w, Ws + (k4 * 4 + 3) * 64);
    }
#pragma unroll
    for (int c = 0; c < 16; c++) {
        float2 a = unpk(acc2[2 * c]), d = unpk(acc2[2 * c + 1]);
        g_t4[r * 16 + c] = make_float4(a.x, a.y, d.x, d.y);
    }
}

// ---------------------------------------------------------------------------
// column sums + sumsq of t  (for BatchNorm batch stats)
// ---------------------------------------------------------------------------
__global__ void k_zero_stats() {
    if (threadIdx.x < 128) g_stats[threadIdx.x] = 0.f;
}

__global__ void k_stats(int n4) {
    __shared__ float sh[8][128];
    int tid = threadIdx.x;
    float s0 = 0, s1 = 0, s2 = 0, s3 = 0, q0 = 0, q1 = 0, q2 = 0, q3 = 0;
    for (int i = blockIdx.x * blockDim.x + tid; i < n4; i += gridDim.x * blockDim.x) {
        float4 v = g_t4[i];
        s0 += v.x; q0 += v.x * v.x;
        s1 += v.y; q1 += v.y * v.y;
        s2 += v.z; q2 += v.z * v.z;
        s3 += v.w; q3 += v.w * v.w;
    }
    s0 += __shfl_down_sync(~0u, s0, 16); s1 += __shfl_down_sync(~0u, s1, 16);
    s2 += __shfl_down_sync(~0u, s2, 16); s3 += __shfl_down_sync(~0u, s3, 16);
    q0 += __shfl_down_sync(~0u, q0, 16); q1 += __shfl_down_sync(~0u, q1, 16);
    q2 += __shfl_down_sync(~0u, q2, 16); q3 += __shfl_down_sync(~0u, q3, 16);
    int lane = tid & 31, warp = tid >> 5;
    if (lane < 16) {
        int base = lane * 8;
        sh[warp][base + 0] = s0; sh[warp][base + 1] = s1;
        sh[warp][base + 2] = s2; sh[warp][base + 3] = s3;
        sh[warp][base + 4] = q0; sh[warp][base + 5] = q1;
        sh[warp][base + 6] = q2; sh[warp][base + 7] = q3;
    }
    __syncthreads();
    if (tid < 128) {
        float tot = 0;
#pragma unroll
        for (int w = 0; w < 8; w++) tot += sh[w][tid];
        int g = tid >> 3, v = tid & 7;
        int c = g * 4 + (v & 3);
        atomicAdd(&g_stats[(v < 4 ? 0 : 64) + c], tot);
    }
}

// ---------------------------------------------------------------------------
// GEMM2: h[outIdx] = relu( relu(BN(t)) @ W2 + b2 )   (FFMA2)
// ---------------------------------------------------------------------------
__global__ void __launch_bounds__(256, 2)
k_gemm2(int outIdx, const float* __restrict__ W, const float* __restrict__ b,
        const float* __restrict__ gam, const float* __restrict__ bet,
        int N, float invN) {
    __shared__ __align__(16) float Ws[64 * 64];
    __shared__ __align__(16) float bs[64], sc[64], sf[64];
    int tid = threadIdx.x;
    for (int i = tid; i < 1024; i += 256)
        ((float4*)Ws)[i] = ((const float4*)W)[i];
    if (tid < 64) {
        bs[tid] = b[tid];
        float mu = g_stats[tid] * invN;
        float var = g_stats[64 + tid] * invN - mu * mu;
        float s = gam[tid] * rsqrtf(var + 1e-5f);
        sc[tid] = s;
        sf[tid] = bet[tid] - mu * s;
    }
    __syncthreads();

    int r = blockIdx.x * 256 + tid;
    if (r >= N) return;

    unsigned long long acc2[32];
#pragma unroll
    for (int c = 0; c < 16; c++) {
        float4 bv = ((const float4*)bs)[c];
        acc2[2 * c]     = pack2(bv.x, bv.y);
        acc2[2 * c + 1] = pack2(bv.z, bv.w);
    }

#pragma unroll
    for (int k4 = 0; k4 < 16; k4++) {
        float4 tv = g_t4[r * 16 + k4];
        float4 c4 = ((const float4*)sc)[k4];
        float4 f4 = ((const float4*)sf)[k4];
        fma64_2(acc2, fmaxf(fmaf(tv.x, c4.x, f4.x), 0.f), Ws + (k4 * 4 + 0) * 64);
        fma64_2(acc2, fmaxf(fmaf(tv.y, c4.y, f4.y), 0.f), Ws + (k4 * 4 + 1) * 64);
        fma64_2(acc2, fmaxf(fmaf(tv.z, c4.z, f4.z), 0.f), Ws + (k4 * 4 + 2) * 64);
        fma64_2(acc2, fmaxf(fmaf(tv.w, c4.w, f4.w), 0.f), Ws + (k4 * 4 + 3) * 64);
    }
#pragma unroll
    for (int c = 0; c < 16; c++) {
        float2 a = unpk(acc2[2 * c]), d = unpk(acc2[2 * c + 1]);
        g_h4[outIdx][r * 16 + c] = make_float4(fmaxf(a.x, 0.f), fmaxf(a.y, 0.f),
                                               fmaxf(d.x, 0.f), fmaxf(d.y, 0.f));
    }
}

// ---------------------------------------------------------------------------
// Final MLP GEMM1: t = concat(x, h1..h5) @ mlpW1[384][64] + b1  (chunked K)
// ---------------------------------------------------------------------------
__global__ void __launch_bounds__(256, 2)
k_gemmF1(const float4* __restrict__ x4, const float* __restrict__ W,
         const float* __restrict__ b, int N) {
    __shared__ __align__(16) float Ws[64 * 64];
    __shared__ __align__(16) float bs[64];
    int tid = threadIdx.x;
    if (tid < 64) bs[tid] = b[tid];
    __syncthreads();

    int r = blockIdx.x * 256 + tid;
    bool act = (r < N);
    unsigned long long acc2[32];
    if (act) {
#pragma unroll
        for (int c = 0; c < 16; c++) {
            float4 bv = ((const float4*)bs)[c];
            acc2[2 * c]     = pack2(bv.x, bv.y);
            acc2[2 * c + 1] = pack2(bv.z, bv.w);
        }
    }

    for (int blk = 0; blk < 6; blk++) {
        __syncthreads();
        for (int i = tid; i < 1024; i += 256)
            ((float4*)Ws)[i] = ((const float4*)(W + blk * 4096))[i];
        __syncthreads();
        const float4* src4 = (blk == 0) ? x4 : (const float4*)g_h4[blk - 1];
        if (act) {
#pragma unroll
            for (int k4 = 0; k4 < 16; k4++) {
                float4 z = src4[r * 16 + k4];
                fma64_2(acc2, z.x, Ws + (k4 * 4 + 0) * 64);
                fma64_2(acc2, z.y, Ws + (k4 * 4 + 1) * 64);
                fma64_2(acc2, z.z, Ws + (k4 * 4 + 2) * 64);
                fma64_2(acc2, z.w, Ws + (k4 * 4 + 3) * 64);
            }
        }
    }
    if (act) {
#pragma unroll
        for (int c = 0; c < 16; c++) {
            float2 a = unpk(acc2[2 * c]), d = unpk(acc2[2 * c + 1]);
            g_t4[r * 16 + c] = make_float4(a.x, a.y, d.x, d.y);
        }
    }
}

// ---------------------------------------------------------------------------
// Final MLP GEMM2 + global add pool
// ---------------------------------------------------------------------------
__global__ void __launch_bounds__(256, 2)
k_gemmF2(const float* __restrict__ W, const float* __restrict__ b,
         const float* __restrict__ gam, const float* __restrict__ bet,
         float* __restrict__ out, int N, float invN) {
    __shared__ __align__(16) float Ws[64 * 64];
    __shared__ __align__(16) float bs[64], sc[64], sf[64];
    int tid = threadIdx.x;
    for (int i = tid; i < 1024; i += 256)
        ((float4*)Ws)[i] = ((const float4*)W)[i];
    if (tid < 64) {
        bs[tid] = b[tid];
        float mu = g_stats[tid] * invN;
        float var = g_stats[64 + tid] * invN - mu * mu;
        float s = gam[tid] * rsqrtf(var + 1e-5f);
        sc[tid] = s;
        sf[tid] = bet[tid] - mu * s;
    }
    __syncthreads();

    int r = blockIdx.x * 256 + tid;
    if (r >= N) return;

    unsigned long long acc2[32];
#pragma unroll
    for (int c = 0; c < 16; c++) {
        float4 bv = ((const float4*)bs)[c];
        acc2[2 * c]     = pack2(bv.x, bv.y);
        acc2[2 * c + 1] = pack2(bv.z, bv.w);
    }

#pragma unroll
    for (int k4 = 0; k4 < 16; k4++) {
        float4 tv = g_t4[r * 16 + k4];
        float4 c4 = ((const float4*)sc)[k4];
        float4 f4 = ((const float4*)sf)[k4];
        fma64_2(acc2, fmaxf(fmaf(tv.x, c4.x, f4.x), 0.f), Ws + (k4 * 4 + 0) * 64);
        fma64_2(acc2, fmaxf(fmaf(tv.y, c4.y, f4.y), 0.f), Ws + (k4 * 4 + 1) * 64);
        fma64_2(acc2, fmaxf(fmaf(tv.z, c4.z, f4.z), 0.f), Ws + (k4 * 4 + 2) * 64);
        fma64_2(acc2, fmaxf(fmaf(tv.w, c4.w, f4.w), 0.f), Ws + (k4 * 4 + 3) * 64);
    }

    int grp = __ldg(&g_batch[r]);
    float* o = out + grp * 64;
#pragma unroll
    for (int c = 0; c < 16; c++) {
        float2 a = unpk(acc2[2 * c]), d = unpk(acc2[2 * c + 1]);
        red_add_v4(o + c * 4, a.x, a.y, d.x, d.y);
    }
}

// ---------------------------------------------------------------------------
// launch
// ---------------------------------------------------------------------------
extern "C" void kernel_launch(void* const* d_in, const int* in_sizes, int n_in,
                              void* d_out, int out_size) {
    const float* x      = (const float*)d_in[0];
    const void*  ei     = d_in[1];
    const void*  batch  = d_in[2];
    const float* convW1 = (const float*)d_in[3];
    const float* convb1 = (const float*)d_in[4];
    const float* convg  = (const float*)d_in[5];
    const float* convbt = (const float*)d_in[6];
    const float* convW2 = (const float*)d_in[7];
    const float* convb2 = (const float*)d_in[8];
    const float* mlpW1  = (const float*)d_in[9];
    const float* mlpb1  = (const float*)d_in[10];
    const float* mlpg   = (const float*)d_in[11];
    const float* mlpbt  = (const float*)d_in[12];
    const float* mlpW2  = (const float*)d_in[13];
    const float* mlpb2  = (const float*)d_in[14];

    int N = in_sizes[0] / HDIM;
    int E = in_sizes[1] / 2;

    const int NB  = (N + 255) / 256;
    const int EB  = (E + 255) / 256;
    const int GB  = (N * 16 + 255) / 256;
    const int CB  = ((E > N ? E : N) + 255) / 256;
    const int SB  = (N + 255) / 256;   // scan blocks (<=256 required)
    const float invN = 1.0f / (float)N;

    cudaMemsetAsync(d_out, 0, (size_t)out_size * sizeof(float));

    // normalize index dtype (int32 vs int64) into int32 scratch
    int probe_words = 4096;
    if (probe_words > 2 * E) probe_words = 2 * E;
    k_probe<<<1, 256>>>((const unsigned int*)ei, probe_words);
    k_convert<<<CB, 256>>>(ei, batch, E, N);

    // CSR build (per call; graph static so identical every call)
    k_zero_cnt<<<NB, 256>>>(N);
    k_hist<<<EB, 256>>>(E);
    k_scan1<<<SB, 256>>>(N);
    k_scan2<<<1, 256>>>(SB);
    k_scan3<<<SB, 256>>>(N);
    k_scatter<<<EB, 256>>>(E);

    for (int l = 0; l < 5; l++) {
        int hidx = l - 1;                       // -1 -> x, else g_h4[l-1]
        k_gather<<<GB, 256>>>(hidx, (const float4*)x, N);
        k_gemm1<<<NB, 256>>>(convW1 + l * 4096, convb1 + l * 64, N);
        k_zero_stats<<<1, 128>>>();
        k_stats<<<256, 256>>>(N * 16);
        k_gemm2<<<NB, 256>>>(l, convW2 + l * 4096, convb2 + l * 64,
                             convg + l * 64, convbt + l * 64, N, invN);
    }

    // final MLP + pool
    k_gemmF1<<<NB, 256>>>((const float4*)x, mlpW1, mlpb1, N);
    k_zero_stats<<<1, 128>>>();
    k_stats<<<256, 256>>>(N * 16);
    k_gemmF2<<<NB, 256>>>(mlpW2, mlpb2, mlpg, mlpbt, (float*)d_out, N, invN);
}

// round 6
// speedup vs baseline: 2.1858x; 1.8473x over previous
#include <cuda_runtime.h>
#include <cuda_bf16.h>
#include <cstdint>

// GIN embedder: CSR gather + mma.sync (HMMA) bf16-split GEMMs, fused BN stats.
// N=50000, E=800000, H=64, 5 layers + JK MLP + pool.

#define HDIM 64
#define NMAX 50000
#define EMAX 800000
#define NV4  (NMAX * 16)

__device__ float4 g_h4[5][NV4];
__device__ float4 g_aggr4[NV4];
__device__ float4 g_t4[NV4];
__device__ float  g_stats[6][128];     // per-stage [sum64, sumsq64]
__device__ int    g_src[EMAX], g_dst[EMAX], g_batch[NMAX], g_is64;
__device__ int    g_cnt[NMAX], g_rowptr[NMAX + 1], g_cursor[NMAX], g_csr[EMAX], g_bsum[256];

// ---------------------------------------------------------------------------
// mma helpers
// ---------------------------------------------------------------------------
__device__ __forceinline__ void mma16816(float* c, uint32_t a0, uint32_t a1,
                                         uint32_t a2, uint32_t a3,
                                         uint32_t b0, uint32_t b1) {
    asm volatile(
        "mma.sync.aligned.m16n8k16.row.col.f32.bf16.bf16.f32 "
        "{%0,%1,%2,%3}, {%4,%5,%6,%7}, {%8,%9}, {%0,%1,%2,%3};"
        : "+f"(c[0]), "+f"(c[1]), "+f"(c[2]), "+f"(c[3])
        : "r"(a0), "r"(a1), "r"(a2), "r"(a3), "r"(b0), "r"(b1));
}

// split (x,y) fp32 pair into bf16x2 hi + bf16x2 lo (residual)
__device__ __forceinline__ void split2(float x, float y, uint32_t& hi, uint32_t& lo) {
    __nv_bfloat16 hx = __float2bfloat16_rn(x), hy = __float2bfloat16_rn(y);
    __nv_bfloat162 ph; ph.x = hx; ph.y = hy;
    hi = *reinterpret_cast<uint32_t*>(&ph);
    __nv_bfloat162 pl;
    pl.x = __float2bfloat16_rn(x - __bfloat162float(hx));
    pl.y = __float2bfloat16_rn(y - __bfloat162float(hy));
    lo = *reinterpret_cast<uint32_t*>(&pl);
}

// Stage W[64][64] (k-major, row k) into smem as pre-packed B fragments.
// Word layout: idx(ks,nt,lane,i) = ((ks*8+nt)*32 + lane)*2 + i ; hi at [w], lo at [2048+w].
__device__ __forceinline__ void stage_B(const float* __restrict__ W,
                                        uint32_t* Bf, int tid) {
    for (int w = tid; w < 2048; w += 256) {
        int i    = w & 1;
        int lane = (w >> 1) & 31;
        int ntks = w >> 6;            // ks*8 + nt
        int t = lane & 3, g = lane >> 2;
        int k = (ntks >> 3) * 16 + 2 * t + i * 8;
        int n = (ntks & 7) * 8 + g;
        float w0 = __ldg(&W[k * 64 + n]);
        float w1 = __ldg(&W[(k + 1) * 64 + n]);
        uint32_t hi, lo;
        split2(w0, w1, hi, lo);
        Bf[w] = hi;
        Bf[2048 + w] = lo;
    }
}

// one K=16 step: convert A pairs, run 8 n-tiles x 3 split-terms
__device__ __forceinline__ void kstep_mma(float c[8][4], const uint32_t* Bf,
                                          int ks, int lane,
                                          float2 x0, float2 x1, float2 x2, float2 x3) {
    uint32_t ah0, al0, ah1, al1, ah2, al2, ah3, al3;
    split2(x0.x, x0.y, ah0, al0);   // A[r0][c0,c0+1]
    split2(x1.x, x1.y, ah1, al1);   // A[r1][c0,c0+1]
    split2(x2.x, x2.y, ah2, al2);   // A[r0][c2,c2+1]
    split2(x3.x, x3.y, ah3, al3);   // A[r1][c2,c2+1]
#pragma unroll
    for (int nt = 0; nt < 8; nt++) {
        int idx = ((ks * 8 + nt) * 32 + lane) * 2;
        uint2 bh = *(const uint2*)&Bf[idx];
        uint2 bl = *(const uint2*)&Bf[2048 + idx];
        mma16816(c[nt], ah0, ah1, ah2, ah3, bh.x, bh.y);
        mma16816(c[nt], ah0, ah1, ah2, ah3, bl.x, bl.y);
        mma16816(c[nt], al0, al1, al2, al3, bh.x, bh.y);
    }
}

__device__ __forceinline__ void red_add_v2(float* p, float a, float b) {
    asm volatile("red.global.add.v2.f32 [%0], {%1,%2};"
                 :: "l"(p), "f"(a), "f"(b) : "memory");
}

// ---------------------------------------------------------------------------
// GEMM1: t = aggr @ W1 + b1  (+ fused BN batch stats into g_stats[slot])
// CTA: 256 threads = 8 warps = 128 rows.
// ---------------------------------------------------------------------------
__global__ void __launch_bounds__(256)
k_mma1(const float* __restrict__ W, const float* __restrict__ bias, int slot, int N) {
    __shared__ __align__(16) uint32_t Bf[4096];
    __shared__ float sb[64];
    __shared__ float sstat[128];
    int tid = threadIdx.x, lane = tid & 31, warp = tid >> 5;
    int t = lane & 3, g = lane >> 2;
    stage_B(W, Bf, tid);
    if (tid < 64) sb[tid] = bias[tid];
    if (tid < 128) sstat[tid] = 0.f;
    __syncthreads();

    int r0 = blockIdx.x * 128 + warp * 16 + g;
    int r1 = r0 + 8;
    bool v0 = r0 < N, v1 = r1 < N;
    const float* p0 = (const float*)g_aggr4 + (size_t)(v0 ? r0 : 0) * 64;
    const float* p1 = (const float*)g_aggr4 + (size_t)(v1 ? r1 : 0) * 64;

    float c[8][4];
#pragma unroll
    for (int i = 0; i < 8; i++) { c[i][0] = c[i][1] = c[i][2] = c[i][3] = 0.f; }

#pragma unroll
    for (int ks = 0; ks < 4; ks++) {
        int c0 = ks * 16 + 2 * t, c2 = c0 + 8;
        float2 z = make_float2(0.f, 0.f);
        float2 x0 = v0 ? *(const float2*)(p0 + c0) : z;
        float2 x1 = v1 ? *(const float2*)(p1 + c0) : z;
        float2 x2 = v0 ? *(const float2*)(p0 + c2) : z;
        float2 x3 = v1 ? *(const float2*)(p1 + c2) : z;
        kstep_mma(c, Bf, ks, lane, x0, x1, x2, x3);
    }

    float* t0 = (float*)g_t4 + (size_t)r0 * 64;
    float* t1 = (float*)g_t4 + (size_t)r1 * 64;
#pragma unroll
    for (int nt = 0; nt < 8; nt++) {
        int n0 = nt * 8 + 2 * t;
        float b0v = sb[n0], b1v = sb[n0 + 1];
        float o0 = c[nt][0] + b0v, o1 = c[nt][1] + b1v;   // row r0
        float o2 = c[nt][2] + b0v, o3 = c[nt][3] + b1v;   // row r1
        if (v0) *(float2*)(t0 + n0) = make_float2(o0, o1);
        if (v1) *(float2*)(t1 + n0) = make_float2(o2, o3);
        float s0 = (v0 ? o0 : 0.f) + (v1 ? o2 : 0.f);
        float s1 = (v0 ? o1 : 0.f) + (v1 ? o3 : 0.f);
        float q0 = (v0 ? o0 * o0 : 0.f) + (v1 ? o2 * o2 : 0.f);
        float q1 = (v0 ? o1 * o1 : 0.f) + (v1 ? o3 * o3 : 0.f);
#pragma unroll
        for (int off = 4; off < 32; off <<= 1) {
            s0 += __shfl_xor_sync(~0u, s0, off);
            s1 += __shfl_xor_sync(~0u, s1, off);
            q0 += __shfl_xor_sync(~0u, q0, off);
            q1 += __shfl_xor_sync(~0u, q1, off);
        }
        if (g == 0) {
            atomicAdd(&sstat[n0], s0);       atomicAdd(&sstat[n0 + 1], s1);
            atomicAdd(&sstat[64 + n0], q0);  atomicAdd(&sstat[64 + n0 + 1], q1);
        }
    }
    __syncthreads();
    if (tid < 128) atomicAdd(&g_stats[slot][tid], sstat[tid]);
}

// ---------------------------------------------------------------------------
// GEMM2: o = relu(BN(t)) @ W2 + b2
//   mode 0: h[outIdx] = relu(o)     mode 1: pool: out[batch[r]] += o
// ---------------------------------------------------------------------------
__global__ void __launch_bounds__(256)
k_mma2(const float* __restrict__ W, const float* __restrict__ bias,
       const float* __restrict__ gam, const float* __restrict__ bet,
       int slot, int outIdx, float invN, int N, int mode, float* __restrict__ pool_out) {
    __shared__ __align__(16) uint32_t Bf[4096];
    __shared__ float sb[64], sc[64], sf[64];
    int tid = threadIdx.x, lane = tid & 31, warp = tid >> 5;
    int t = lane & 3, g = lane >> 2;
    stage_B(W, Bf, tid);
    if (tid < 64) {
        sb[tid] = bias[tid];
        float mu = g_stats[slot][tid] * invN;
        float var = g_stats[slot][64 + tid] * invN - mu * mu;
        float s = gam[tid] * rsqrtf(var + 1e-5f);
        sc[tid] = s;
        sf[tid] = bet[tid] - mu * s;
    }
    __syncthreads();

    int r0 = blockIdx.x * 128 + warp * 16 + g;
    int r1 = r0 + 8;
    bool v0 = r0 < N, v1 = r1 < N;
    const float* p0 = (const float*)g_t4 + (size_t)(v0 ? r0 : 0) * 64;
    const float* p1 = (const float*)g_t4 + (size_t)(v1 ? r1 : 0) * 64;

    float c[8][4];
#pragma unroll
    for (int i = 0; i < 8; i++) { c[i][0] = c[i][1] = c[i][2] = c[i][3] = 0.f; }

#pragma unroll
    for (int ks = 0; ks < 4; ks++) {
        int c0 = ks * 16 + 2 * t, c2 = c0 + 8;
        float2 sc0 = *(const float2*)(sc + c0), sf0 = *(const float2*)(sf + c0);
        float2 sc2 = *(const float2*)(sc + c2), sf2 = *(const float2*)(sf + c2);
        float2 z = make_float2(0.f, 0.f);
        float2 x0 = v0 ? *(const float2*)(p0 + c0) : z;
        float2 x1 = v1 ? *(const float2*)(p1 + c0) : z;
        float2 x2 = v0 ? *(const float2*)(p0 + c2) : z;
        float2 x3 = v1 ? *(const float2*)(p1 + c2) : z;
        x0.x = fmaxf(fmaf(x0.x, sc0.x, sf0.x), 0.f); x0.y = fmaxf(fmaf(x0.y, sc0.y, sf0.y), 0.f);
        x1.x = fmaxf(fmaf(x1.x, sc0.x, sf0.x), 0.f); x1.y = fmaxf(fmaf(x1.y, sc0.y, sf0.y), 0.f);
        x2.x = fmaxf(fmaf(x2.x, sc2.x, sf2.x), 0.f); x2.y = fmaxf(fmaf(x2.y, sc2.y, sf2.y), 0.f);
        x3.x = fmaxf(fmaf(x3.x, sc2.x, sf2.x), 0.f); x3.y = fmaxf(fmaf(x3.y, sc2.y, sf2.y), 0.f);
        kstep_mma(c, Bf, ks, lane, x0, x1, x2, x3);
    }

#pragma unroll
    for (int nt = 0; nt < 8; nt++) {
        int n0 = nt * 8 + 2 * t;
        float b0v = sb[n0], b1v = sb[n0 + 1];
        float o0 = c[nt][0] + b0v, o1 = c[nt][1] + b1v;
        float o2 = c[nt][2] + b0v, o3 = c[nt][3] + b1v;
        if (mode == 0) {
            float* h0 = (float*)g_h4[outIdx] + (size_t)r0 * 64;
            float* h1 = (float*)g_h4[outIdx] + (size_t)r1 * 64;
            if (v0) *(float2*)(h0 + n0) = make_float2(fmaxf(o0, 0.f), fmaxf(o1, 0.f));
            if (v1) *(float2*)(h1 + n0) = make_float2(fmaxf(o2, 0.f), fmaxf(o3, 0.f));
        } else {
            if (v0) {
                int gr = __ldg(&g_batch[r0]);
                red_add_v2(pool_out + gr * 64 + n0, o0, o1);
            }
            if (v1) {
                int gr = __ldg(&g_batch[r1]);
                red_add_v2(pool_out + gr * 64 + n0, o2, o3);
            }
        }
    }
}

// ---------------------------------------------------------------------------
// Final MLP GEMM1: t = concat(x, h1..h5) @ mlpW1[384,64] + b1 (+ stats slot 5)
// ---------------------------------------------------------------------------
__global__ void __launch_bounds__(256)
k_mmaF1(const float* __restrict__ x, const float* __restrict__ W,
        const float* __restrict__ bias, int N) {
    __shared__ __align__(16) uint32_t Bf[4096];
    __shared__ float sb[64];
    __shared__ float sstat[128];
    int tid = threadIdx.x, lane = tid & 31, warp = tid >> 5;
    int t = lane & 3, g = lane >> 2;
    if (tid < 64) sb[tid] = bias[tid];
    if (tid < 128) sstat[tid] = 0.f;

    int r0 = blockIdx.x * 128 + warp * 16 + g;
    int r1 = r0 + 8;
    bool v0 = r0 < N, v1 = r1 < N;

    float c[8][4];
#pragma unroll
    for (int i = 0; i < 8; i++) { c[i][0] = c[i][1] = c[i][2] = c[i][3] = 0.f; }

    for (int blk = 0; blk < 6; blk++) {
        __syncthreads();                      // prior Bf reads done / init done
        stage_B(W + blk * 4096, Bf, tid);
        __syncthreads();
        const float* base = (blk == 0) ? x : (const float*)g_h4[blk - 1];
        const float* p0 = base + (size_t)(v0 ? r0 : 0) * 64;
        const float* p1 = base + (size_t)(v1 ? r1 : 0) * 64;
#pragma unroll
        for (int ks = 0; ks < 4; ks++) {
            int c0 = ks * 16 + 2 * t, c2 = c0 + 8;
            float2 z = make_float2(0.f, 0.f);
            float2 x0 = v0 ? *(const float2*)(p0 + c0) : z;
            float2 x1 = v1 ? *(const float2*)(p1 + c0) : z;
            float2 x2 = v0 ? *(const float2*)(p0 + c2) : z;
            float2 x3 = v1 ? *(const float2*)(p1 + c2) : z;
            kstep_mma(c, Bf, ks, lane, x0, x1, x2, x3);
        }
    }

    float* t0 = (float*)g_t4 + (size_t)r0 * 64;
    float* t1 = (float*)g_t4 + (size_t)r1 * 64;
#pragma unroll
    for (int nt = 0; nt < 8; nt++) {
        int n0 = nt * 8 + 2 * t;
        float b0v = sb[n0], b1v = sb[n0 + 1];
        float o0 = c[nt][0] + b0v, o1 = c[nt][1] + b1v;
        float o2 = c[nt][2] + b0v, o3 = c[nt][3] + b1v;
        if (v0) *(float2*)(t0 + n0) = make_float2(o0, o1);
        if (v1) *(float2*)(t1 + n0) = make_float2(o2, o3);
        float s0 = (v0 ? o0 : 0.f) + (v1 ? o2 : 0.f);
        float s1 = (v0 ? o1 : 0.f) + (v1 ? o3 : 0.f);
        float q0 = (v0 ? o0 * o0 : 0.f) + (v1 ? o2 * o2 : 0.f);
        float q1 = (v0 ? o1 * o1 : 0.f) + (v1 ? o3 * o3 : 0.f);
#pragma unroll
        for (int off = 4; off < 32; off <<= 1) {
            s0 += __shfl_xor_sync(~0u, s0, off);
            s1 += __shfl_xor_sync(~0u, s1, off);
            q0 += __shfl_xor_sync(~0u, q0, off);
            q1 += __shfl_xor_sync(~0u, q1, off);
        }
        if (g == 0) {
            atomicAdd(&sstat[n0], s0);       atomicAdd(&sstat[n0 + 1], s1);
            atomicAdd(&sstat[64 + n0], q0);  atomicAdd(&sstat[64 + n0 + 1], q1);
        }
    }
    __syncthreads();
    if (tid < 128) atomicAdd(&g_stats[5][tid], sstat[tid]);
}

// ---------------------------------------------------------------------------
// index normalize + CSR build
// ---------------------------------------------------------------------------
__global__ void k_probe(const unsigned int* __restrict__ ei_raw, int nwords) {
    __shared__ int any_nonzero;
    if (threadIdx.x == 0) any_nonzero = 0;
    __syncthreads();
    for (int i = threadIdx.x; i < nwords / 2; i += blockDim.x)
        if (ei_raw[2 * i + 1] != 0u) any_nonzero = 1;
    __syncthreads();
    if (threadIdx.x == 0) g_is64 = any_nonzero ? 0 : 1;
}

__global__ void k_convert(const void* __restrict__ ei, const void* __restrict__ batch,
                          int E, int N) {
    int i = blockIdx.x * blockDim.x + threadIdx.x;
    bool is64 = (g_is64 != 0);
    if (i < E) {
        if (is64) {
            g_src[i] = (int)((const long long*)ei)[i];
            g_dst[i] = (int)((const long long*)ei)[E + i];
        } else {
            g_src[i] = ((const int*)ei)[i];
            g_dst[i] = ((const int*)ei)[E + i];
        }
    }
    if (i < N) {
        g_batch[i] = is64 ? (int)((const long long*)batch)[i] : ((const int*)batch)[i];
        g_cnt[i] = 0;
    }
    if (i < 768) ((float*)g_stats)[i] = 0.f;
}

__global__ void k_hist(int E) {
    int e = blockIdx.x * blockDim.x + threadIdx.x;
    if (e < E) atomicAdd(&g_cnt[g_dst[e]], 1);
}

__global__ void k_scan1(int N) {
    __shared__ int sh[256];
    int i = blockIdx.x * 256 + threadIdx.x;
    sh[threadIdx.x] = (i < N) ? g_cnt[i] : 0;
    __syncthreads();
    for (int s = 128; s > 0; s >>= 1) {
        if (threadIdx.x < s) sh[threadIdx.x] += sh[threadIdx.x + s];
        __syncthreads();
    }
    if (threadIdx.x == 0) g_bsum[blockIdx.x] = sh[0];
}

__global__ void k_scan2(int nblk) {
    __shared__ int a[256], b[256];
    int t = threadIdx.x;
    a[t] = (t < nblk) ? g_bsum[t] : 0;
    __syncthreads();
    int* cur = a; int* nxt = b;
    for (int off = 1; off < 256; off <<= 1) {
        nxt[t] = cur[t] + ((t >= off) ? cur[t - off] : 0);
        __syncthreads();
        int* tmp = cur; cur = nxt; nxt = tmp;
    }
    __syncthreads();
    if (t < nblk) g_bsum[t] = (t == 0) ? 0 : cur[t - 1];
}

__global__ void k_scan3(int N) {
    __shared__ int a[256], b[256];
    int t = threadIdx.x;
    int i = blockIdx.x * 256 + t;
    int v = (i < N) ? g_cnt[i] : 0;
    a[t] = v;
    __syncthreads();
    int* cur = a; int* nxt = b;
    for (int off = 1; off < 256; off <<= 1) {
        nxt[t] = cur[t] + ((t >= off) ? cur[t - off] : 0);
        __syncthreads();
        int* tmp = cur; cur = nxt; nxt = tmp;
    }
    int row = g_bsum[blockIdx.x] + cur[t] - v;
    if (i <= N) {
        g_rowptr[i] = row;
        if (i < N) g_cursor[i] = row;
    }
}

__global__ void k_scatter(int E) {
    int e = blockIdx.x * blockDim.x + threadIdx.x;
    if (e >= E) return;
    int d = g_dst[e];
    int pos = atomicAdd(&g_cursor[d], 1);
    g_csr[pos] = g_src[e];
}

// ---------------------------------------------------------------------------
// gather: aggr[n] = h[n] + sum_{j in nbrs(n)} h[j]   (16 threads/node)
// ---------------------------------------------------------------------------
__global__ void k_gather(int hidx, const float4* __restrict__ x4, int N) {
    const float4* h4 = (hidx < 0) ? x4 : (const float4*)g_h4[hidx];
    int tid = blockIdx.x * blockDim.x + threadIdx.x;
    int n = tid >> 4;
    if (n >= N) return;
    int j = tid & 15;
    int beg = __ldg(&g_rowptr[n]);
    int end = __ldg(&g_rowptr[n + 1]);
    float4 acc = __ldg(&h4[n * 16 + j]);
    for (int i = beg; i < end; i++) {
        int s = __ldg(&g_csr[i]);
        float4 v = __ldg(&h4[s * 16 + j]);
        acc.x += v.x; acc.y += v.y; acc.z += v.z; acc.w += v.w;
    }
    g_aggr4[n * 16 + j] = acc;
}

// ---------------------------------------------------------------------------
// launch
// ---------------------------------------------------------------------------
extern "C" void kernel_launch(void* const* d_in, const int* in_sizes, int n_in,
                              void* d_out, int out_size) {
    const float* x      = (const float*)d_in[0];
    const void*  ei     = d_in[1];
    const void*  batch  = d_in[2];
    const float* convW1 = (const float*)d_in[3];
    const float* convb1 = (const float*)d_in[4];
    const float* convg  = (const float*)d_in[5];
    const float* convbt = (const float*)d_in[6];
    const float* convW2 = (const float*)d_in[7];
    const float* convb2 = (const float*)d_in[8];
    const float* mlpW1  = (const float*)d_in[9];
    const float* mlpb1  = (const float*)d_in[10];
    const float* mlpg   = (const float*)d_in[11];
    const float* mlpbt  = (const float*)d_in[12];
    const float* mlpW2  = (const float*)d_in[13];
    const float* mlpb2  = (const float*)d_in[14];

    int N = in_sizes[0] / HDIM;
    int E = in_sizes[1] / 2;

    const int TB = (N + 127) / 128;
    const int EB = (E + 255) / 256;
    const int GB = (N * 16 + 255) / 256;
    const int CB = ((E > N ? E : N) + 255) / 256;
    const int SB = (N + 255) / 256;
    const float invN = 1.0f / (float)N;

    cudaMemsetAsync(d_out, 0, (size_t)out_size * sizeof(float));

    int probe_words = 4096;
    if (probe_words > 2 * E) probe_words = 2 * E;
    k_probe<<<1, 256>>>((const unsigned int*)ei, probe_words);
    k_convert<<<CB, 256>>>(ei, batch, E, N);

    k_hist<<<EB, 256>>>(E);
    k_scan1<<<SB, 256>>>(N);
    k_scan2<<<1, 256>>>(SB);
    k_scan3<<<SB, 256>>>(N);
    k_scatter<<<EB, 256>>>(E);

    for (int l = 0; l < 5; l++) {
        k_gather<<<GB, 256>>>(l - 1, (const float4*)x, N);
        k_mma1<<<TB, 256>>>(convW1 + l * 4096, convb1 + l * 64, l, N);
        k_mma2<<<TB, 256>>>(convW2 + l * 4096, convb2 + l * 64,
                            convg + l * 64, convbt + l * 64,
                            l, l, invN, N, 0, nullptr);
    }

    k_mmaF1<<<TB, 256>>>(x, mlpW1, mlpb1, N);
    k_mma2<<<TB, 256>>>(mlpW2, mlpb2, mlpg, mlpbt,
                        5, 0, invN, N, 1, (float*)d_out);
}